// round 10
// baseline (speedup 1.0000x reference)
#include <cuda_runtime.h>

// VolumeRotation: B=8, C=16, S=64 — smem-tiled trilinear gather, round 9.
// 1024-thread block = TWO independent 512-thread groups (named barriers),
// each owning a 16x16x8 z-half sub-tile with its own 86528 B single-buffered
// window. Groups' fill latencies hide behind each other's gathers.

#define SB 64
#define CB 16
#define S3 (SB*SB*SB)
#define NTHR 1024
#define GTHR 512
#define SPT 4                    // 2048 sub-voxels / 512 threads
#define WW 26                    // y,z window cells per sub-tile
#define NROWS (WW*WW)            // 676
#define WIN_BYTES (NROWS*128)    // 86528
#define SMEM_BYTES (2*WIN_BYTES) // 173056
#define SLOTS 11                 // rows 0..675, 64 rows per slot

__device__ __forceinline__ void sample_pos(
    float r00, float r01, float r02,
    float r10, float r11, float r12,
    float r20, float r21, float r22,
    int x, int y, int z,
    float& fx, float& fy, float& fz)
{
    const float sc = 2.0f / 63.0f;
    float bx = fmaf((float)x, sc, -1.0f);
    float by = fmaf((float)y, sc, -1.0f);
    float bz = fmaf((float)z, sc, -1.0f);
    float gx = fmaf(r00, bx, fmaf(r10, by, r20 * bz));
    float gy = fmaf(r01, bx, fmaf(r11, by, r21 * bz));
    float gz = fmaf(r02, bx, fmaf(r12, by, r22 * bz));
    fx = fmaf(gx, 32.0f, 31.5f);
    fy = fmaf(gy, 32.0f, 31.5f);
    fz = fmaf(gz, 32.0f, 31.5f);
}

__global__ __launch_bounds__(NTHR, 1)
void volrot_kernel(const float* __restrict__ vol,
                   const float* __restrict__ rot,
                   float* __restrict__ out)
{
    extern __shared__ float smemf[];

    int tid = threadIdx.x;
    int gid = tid >> 9;               // group 0 / 1
    int ltid = tid & 511;
    unsigned gbase = (unsigned)(gid * WIN_BYTES);
    const char* wb = (const char*)smemf + gbase;
    unsigned su = (unsigned)__cvta_generic_to_shared(smemf) + gbase;
    unsigned barid = (unsigned)(gid + 1);

    int blk = blockIdx.x;
    int b = blk >> 6;                 // 64 tiles per batch
    int t = blk & 63;
    int oz = (t >> 4) * 16 + gid * 8; // sub-tile z origin
    int oy = ((t >> 2) & 3) * 16;
    int ox = (t & 3) * 16;

    const float* R = rot + b * 9;
    float r00 = __ldg(R+0), r01 = __ldg(R+1), r02 = __ldg(R+2);
    float r10 = __ldg(R+3), r11 = __ldg(R+4), r12 = __ldg(R+5);
    float r20 = __ldg(R+6), r21 = __ldg(R+7), r22 = __ldg(R+8);

    // min/max sample coords over the 8 SUB-tile corners
    float mnx = 1e30f, mny = 1e30f, mnz = 1e30f;
    float mxx = -1e30f, mxy = -1e30f, mxz = -1e30f;
    #pragma unroll
    for (int k = 0; k < 8; k++) {
        int cx = ox + ((k & 1) ? 15 : 0);
        int cy = oy + ((k & 2) ? 15 : 0);
        int cz = oz + ((k & 4) ? 7 : 0);
        float fx, fy, fz;
        sample_pos(r00,r01,r02,r10,r11,r12,r20,r21,r22, cx, cy, cz, fx, fy, fz);
        mnx = fminf(mnx, fx); mny = fminf(mny, fy); mnz = fminf(mnz, fz);
        mxx = fmaxf(mxx, fx); mxy = fmaxf(mxy, fy); mxz = fmaxf(mxz, fz);
    }
    int bax = ((int)floorf(mnx)) & ~3;
    int bay = (int)floorf(mny);
    int baz = (int)floorf(mnz);
    int exMax = ((int)floorf(mxx)) + 1 - bax;
    int eyMax = ((int)floorf(mxy)) + 1 - bay;
    int ezMax = ((int)floorf(mxz)) + 1 - baz;

    // ---- staging masks (channel-invariant): quad = (row = r0+64j, xq)
    int xq = ltid & 7;
    int r0 = ltid >> 3;               // 0..63
    int gxq = bax + (xq << 2);
    unsigned need = 0, inb = 0;
    #pragma unroll
    for (int j = 0; j < SLOTS; j++) {
        int rowid = r0 + j * 64;
        if (rowid < NROWS) {
            int wz = rowid / WW;
            int wy = rowid - wz * WW;
            bool nd = ((xq << 2) <= exMax) & (wy <= eyMax) & (wz <= ezMax);
            int gy = bay + wy, gz = baz + wz;
            bool ok = ((unsigned)gxq <= (unsigned)(SB - 4)) &
                      ((unsigned)gy < (unsigned)SB) &
                      ((unsigned)gz < (unsigned)SB);
            if (nd) need |= (1u << j);
            if (ok) inb  |= (1u << j);
        }
    }
    unsigned sidx0 = (unsigned)(r0 * 128 + ((xq ^ (r0 & 7)) << 4));

    // ---- per-sample channel-invariant state (packed; same scheme as R8)
    unsigned rpk[2], capk[2];
    float ex0[SPT], ex1[SPT], wp0[SPT], wp1[SPT], wp2[SPT], wp3[SPT];
    unsigned obyte0 = 0;
    rpk[0] = rpk[1] = capk[0] = capk[1] = 0;

    #pragma unroll
    for (int s = 0; s < SPT; s++) {
        int v = ltid + s * GTHR;          // 0..2047 within sub-tile
        int lx = v & 15, ly = (v >> 4) & 15, lz = v >> 8;   // lz 0..7
        int x = ox + lx, y = oy + ly, z = oz + lz;
        float fx, fy, fz;
        sample_pos(r00,r01,r02,r10,r11,r12,r20,r21,r22, x, y, z, fx, fy, fz);
        float x0f = floorf(fx), y0f = floorf(fy), z0f = floorf(fz);
        float txf = fx - x0f, tyf = fy - y0f, tzf = fz - z0f;
        int x0 = (int)x0f, y0 = (int)y0f, z0 = (int)z0f;

        ex0[s] = ((unsigned)x0       < (unsigned)SB) ? (1.0f - txf) : 0.0f;
        ex1[s] = ((unsigned)(x0 + 1) < (unsigned)SB) ? txf          : 0.0f;
        bool vy0 = (unsigned)y0       < (unsigned)SB;
        bool vy1 = (unsigned)(y0 + 1) < (unsigned)SB;
        bool vz0 = (unsigned)z0       < (unsigned)SB;
        bool vz1 = (unsigned)(z0 + 1) < (unsigned)SB;
        wp0[s] = (vy0 && vz0) ? (1.0f - tyf) * (1.0f - tzf) : 0.0f;
        wp1[s] = (vy1 && vz0) ? tyf * (1.0f - tzf)          : 0.0f;
        wp2[s] = (vy0 && vz1) ? (1.0f - tyf) * tzf          : 0.0f;
        wp3[s] = (vy1 && vz1) ? tyf * tzf                   : 0.0f;

        int wx0 = min(max(x0 - bax, 0), 26);
        int wy0 = min(max(y0 - bay, 0), WW - 2);
        int wz0 = min(max(z0 - baz, 0), WW - 2);
        unsigned rowid = (unsigned)(wz0 * WW + wy0);        // <= 648
        rpk[s >> 1] |= rowid << ((s & 1) * 16);
        int xa = wx0, xb = wx0 + 1;
        unsigned ca0 = (unsigned)(((xa >> 2) << 4) | ((xa & 3) << 2));
        unsigned ca1 = (unsigned)(((xb >> 2) << 4) | ((xb & 3) << 2));
        capk[s >> 1] |= (ca0 | (ca1 << 8)) << ((s & 1) * 16);
        if (s == 0) obyte0 = (unsigned)((((z * SB) + y) * SB + x) * 4);
    }

    const char* srcb = (const char*)vol + (size_t)b * CB * S3 * 4;
    char*       dstb = (char*)out       + (size_t)b * CB * S3 * 4;

    #pragma unroll 1
    for (int c = 0; c < CB; c++) {
        // ---- fill channel c window (single buffer, own group only)
        {
            const char* g = srcb + (size_t)c * S3 * 4;
            #pragma unroll
            for (int j = 0; j < SLOTS; j++) {
                if ((need >> j) & 1u) {
                    int rowid = r0 + j * 64;
                    int wz = rowid / WW;
                    int wy = rowid - wz * WW;
                    int gy = bay + wy, gz = baz + wz;
                    unsigned ok = (inb >> j) & 1u;
                    unsigned go = ok ? (unsigned)((((gz * SB) + gy) * SB + gxq) * 4) : 0u;
                    unsigned sz = ok << 4;
                    asm volatile("cp.async.cg.shared.global [%0], [%1], 16, %2;"
                        :: "r"(su + sidx0 + (unsigned)(j * 8192)),
                           "l"(g + go), "r"(sz) : "memory");
                }
            }
            asm volatile("cp.async.commit_group;" ::: "memory");
        }
        asm volatile("cp.async.wait_group 0;" ::: "memory");
        asm volatile("bar.sync %0, %1;" :: "r"(barid), "n"(GTHR) : "memory");

        // ---- gather channel c
        char* dc = dstb + (size_t)c * S3 * 4 + obyte0;
        #pragma unroll
        for (int s = 0; s < SPT; s++) {
            unsigned rowid = (rpk[s >> 1] >> ((s & 1) * 16)) & 0xFFFFu;
            unsigned cap   = (capk[s >> 1] >> ((s & 1) * 16)) & 0xFFFFu;
            unsigned ca0 = cap & 0xFFu;
            unsigned ca1 = (cap >> 8) & 0xFFu;

            unsigned rk0 = rowid * 128 + ((rowid & 7) << 4);
            unsigned rr1 = rowid + 1;
            unsigned rk1 = rr1 * 128 + ((rr1 & 7) << 4);
            unsigned rr2 = rowid + WW;
            unsigned rk2 = rr2 * 128 + ((rr2 & 7) << 4);
            unsigned rr3 = rowid + WW + 1;
            unsigned rk3 = rr3 * 128 + ((rr3 & 7) << 4);

            float v00 = *(const float*)(wb + (rk0 ^ ca0));
            float v01 = *(const float*)(wb + (rk0 ^ ca1));
            float v10 = *(const float*)(wb + (rk1 ^ ca0));
            float v11 = *(const float*)(wb + (rk1 ^ ca1));
            float v20 = *(const float*)(wb + (rk2 ^ ca0));
            float v21 = *(const float*)(wb + (rk2 ^ ca1));
            float v30 = *(const float*)(wb + (rk3 ^ ca0));
            float v31 = *(const float*)(wb + (rk3 ^ ca1));

            float e0 = ex0[s], e1 = ex1[s];
            float s0 = fmaf(e0, v00, e1 * v01);
            float s1 = fmaf(e0, v10, e1 * v11);
            float s2 = fmaf(e0, v20, e1 * v21);
            float s3 = fmaf(e0, v30, e1 * v31);
            float acc = wp0[s] * s0;
            acc = fmaf(wp1[s], s1, acc);
            acc = fmaf(wp2[s], s2, acc);
            acc = fmaf(wp3[s], s3, acc);
            *(float*)(dc + (unsigned)(s * 32768)) = acc;   // lz += 2 per s
        }

        asm volatile("bar.sync %0, %1;" :: "r"(barid), "n"(GTHR) : "memory");
    }
}

extern "C" void kernel_launch(void* const* d_in, const int* in_sizes, int n_in,
                              void* d_out, int out_size)
{
    const float* vol = (const float*)d_in[0];   // [8,16,64,64,64] f32
    const float* rot = (const float*)d_in[1];   // [8,3,3] f32
    float* out = (float*)d_out;

    cudaFuncSetAttribute(volrot_kernel,
                         cudaFuncAttributeMaxDynamicSharedMemorySize, SMEM_BYTES);

    volrot_kernel<<<8 * 64, NTHR, SMEM_BYTES>>>(vol, rot, out);
}